// round 16
// baseline (speedup 1.0000x reference)
#include <cuda_runtime.h>
#include <cuda_bf16.h>
#include <cstdint>

#define CI 128
#define CO 128
#define NE 4
#define NB 5               // 4 experts + 1 "unmatched" bucket
#define MAXROWS (2048*128)
#define BM 64               // rows per tile (2 CTAs/SM)
#define NCTA 304            // 2 persistent CTAs per SM
#define NT 512              // 8 producer warps + 8 consumer warps
#define NSTG 3              // x-tile ring depth

// ---------------- scratch (__device__ globals; no dynamic alloc allowed) ----
__device__ int g_row_idx[NB][MAXROWS];
__device__ int g_count[NB];   // zeroed at load; re-zeroed by k_gemm tail
__device__ __align__(16) unsigned char g_wimg_hi[NE][32768];
__device__ __align__(16) unsigned char g_wimg_lo[NE][32768];

// ---------------- small helpers ---------------------------------------------
__device__ __forceinline__ uint32_t smem_u32(const void* p) {
    uint32_t a;
    asm("{ .reg .u64 t; cvta.to.shared.u64 t, %1; cvt.u32.u64 %0, t; }"
        : "=r"(a) : "l"(p));
    return a;
}
__device__ __forceinline__ uint32_t swz(uint32_t off) {   // SW128: Swizzle<3,4,3>
    return off ^ ((off >> 3) & 0x70);
}
__device__ __forceinline__ void split2(uint32_t& h, uint32_t& l, float a, float b) {
    asm("cvt.rn.bf16x2.f32 %0, %1, %2;" : "=r"(h) : "f"(b), "f"(a));
    float ra = a - __uint_as_float(h << 16);
    float rb = b - __uint_as_float(h & 0xffff0000u);
    asm("cvt.rn.bf16x2.f32 %0, %1, %2;" : "=r"(l) : "f"(rb), "f"(ra));
}
static __device__ __forceinline__ uint64_t make_desc(uint32_t addr) {
    const uint64_t BASE = (uint64_t(2) << 61) | (uint64_t(1) << 46) |
                          (uint64_t(64) << 32) | (uint64_t(1) << 16);
    return BASE | ((uint64_t)(addr >> 4) & 0x3FFF);
}
// idesc kind::f16: F32 accum, bf16 a/b, N=64 ((64/8)<<17), M=128 ((128/16)<<24)
#define MMA_IDESC 0x8100490u
// byte offset in a [128 x 128] bf16 K-major SW128 blocked tile (W images)
__device__ __forceinline__ uint32_t tile_off_128r(uint32_t row, uint32_t col) {
    return ((row >> 3) + (col >> 6) * 16u) * 1024u + (row & 7u) * 128u + (col & 63u) * 2u;
}
__device__ __forceinline__ void mbar_wait(uint32_t mb, uint32_t par) {
    uint32_t done = 0;
    while (!done) {
        asm volatile(
            "{\n\t.reg .pred p;\n\t"
            "mbarrier.try_wait.parity.acquire.cta.shared::cta.b64 p, [%1], %2, 0x989680;\n\t"
            "selp.b32 %0, 1, 0, p;\n\t}"
            : "=r"(done) : "r"(mb), "r"(par) : "memory");
    }
}

// ---------------- prep: scatter blocks + wprep blocks (NO zeroing) -----------
__global__ void __launch_bounds__(1024)
k_prep(const int* __restrict__ atom_numbers, const int* __restrict__ atom_cases,
       const float* __restrict__ W, int nrows, int nscatter) {
    if ((int)blockIdx.x >= nscatter) {
        int e = blockIdx.x - nscatter;
        const float* We = W + (size_t)e * CI * CO;
        for (int item = threadIdx.x; item < CO * 16; item += 1024) {
            int o = item & 127;
            int kc = item >> 7;
            uint32_t ph[4], pl[4];
#pragma unroll
            for (int j = 0; j < 4; j++) {
                float a = __ldg(We + (kc * 8 + 2 * j) * CO + o);
                float b = __ldg(We + (kc * 8 + 2 * j + 1) * CO + o);
                split2(ph[j], pl[j], a, b);
            }
            uint32_t s = swz(tile_off_128r(o, kc * 8));
            *(uint4*)((unsigned char*)g_wimg_hi[e] + s) =
                make_uint4(ph[0], ph[1], ph[2], ph[3]);
            *(uint4*)((unsigned char*)g_wimg_lo[e] + s) =
                make_uint4(pl[0], pl[1], pl[2], pl[3]);
        }
        return;
    }

    __shared__ int wcnt[NB][32];
    __shared__ int sbase[NB];
    int t = threadIdx.x, w = t >> 5, lane = t & 31;
    int row = blockIdx.x * 1024 + t;
    bool valid = row < nrows;
    int an = valid ? atom_numbers[row] : -1234567;
    int c0 = __ldg(atom_cases + 0), c1 = __ldg(atom_cases + 1);
    int c2 = __ldg(atom_cases + 2), c3 = __ldg(atom_cases + 3);
    int e = 4;
    if (an == c0) e = 0;
    else if (an == c1) e = 1;
    else if (an == c2) e = 2;
    else if (an == c3) e = 3;
    if (!valid) e = -1;

    int myrank = 0;
#pragma unroll
    for (int b = 0; b < NB; b++) {
        unsigned m = __ballot_sync(0xffffffffu, e == b);
        if (e == b) myrank = __popc(m & ((1u << lane) - 1u));
        if (lane == 0) wcnt[b][w] = __popc(m);
    }
    __syncthreads();
    if (t < NB) {
        int s = 0;
#pragma unroll
        for (int i = 0; i < 32; i++) { int v = wcnt[t][i]; wcnt[t][i] = s; s += v; }
        sbase[t] = s ? atomicAdd(&g_count[t], s) : 0;
    }
    __syncthreads();
    if (e >= 0) g_row_idx[e][sbase[e] + wcnt[e][w] + myrank] = row;
}

// ---------------- warp-specialized persistent grouped GEMM (TS, BM=64) --------
// 2 CTAs/SM (launch_bounds(512,2)); per CTA: 3x32KB x ring, TMEM 256 cols
// (D0 0..63, D1 64..127, W_hi 128..191, W_lo 192..255).
// x tile = 64 rows x 128 bf16, K-major SW128 blocked (8 atom-rows per col
// group -> K16-step descriptor offset (k>>2)*512 + (k&3)*2).
#define OFF_A(stg)  ((stg) * 32768u)            // x_hi at +0, x_lo at +16384
#define OFF_CTRL 98304u    // [0]=tmem [8,16,24]=mma mbars [32,40]=epi mbars
#define SMEM_BYTES (98304 + 1024 + 1024)
#define TM_WHI 128u
#define TM_WLO 192u

__global__ void __launch_bounds__(NT, 2)
k_gemm(const float* __restrict__ x, const float* __restrict__ W,
       const float* __restrict__ bias, float* __restrict__ out) {
    int t = threadIdx.x;
    int wid = t >> 5, lane = t & 31;

    int c[NE], pfx[NE + 1];
    pfx[0] = 0;
#pragma unroll
    for (int e = 0; e < NE; e++) {
        c[e] = g_count[e];
        pfx[e + 1] = pfx[e] + ((c[e] + BM - 1) >> 6);
    }
    int total = pfx[NE];
    int begin = (int)((long long)total * blockIdx.x / gridDim.x);
    int end   = (int)((long long)total * (blockIdx.x + 1) / gridDim.x);

    // unmatched-row zero slice for this CTA
    int cnt4 = g_count[4];
    int z0 = (int)((long long)cnt4 * blockIdx.x / gridDim.x);
    int z1 = (int)((long long)cnt4 * (blockIdx.x + 1) / gridDim.x);

#if defined(__CUDA_ARCH__) && !defined(__CUDA_ARCH_FEAT_SM103_ALL)
    // ---------------- fallback: fp32 SIMT (JIT-safety only) ------------------
    for (int i = z0 * 32 + t; i < z1 * 32; i += NT) {
        int grow = g_row_idx[4][i >> 5];
        ((float4*)out)[(size_t)grow * 32 + (i & 31)] = make_float4(0.f, 0.f, 0.f, 0.f);
    }
    for (int tile = begin; tile < end; tile++) {
        int e = 0;
        while (tile >= pfx[e + 1]) e++;
        int m0 = (tile - pfx[e]) * BM;
        int nr = min(BM, c[e] - m0);
        for (int idx = t; idx < nr * CO; idx += NT) {
            int m = idx >> 7, o = idx & 127;
            int grow = g_row_idx[e][m0 + m];
            const float* xr = x + (size_t)grow * CI;
            const float* wc = W + (size_t)e * CI * CO + o;
            float acc = bias[e * CO + o];
            for (int k = 0; k < CI; k++) acc += xr[k] * wc[(size_t)k * CO];
            out[(size_t)grow * CO + o] = fmaxf(acc, 0.f);
        }
    }
    __syncthreads();
    if (blockIdx.x == 0 && t < NB) g_count[t] = 0;
#else
    extern __shared__ unsigned char smraw[];
    uint32_t sraw = smem_u32(smraw);
    uint32_t sbase_a = (sraw + 1023u) & ~1023u;
    unsigned char* sm = smraw + (sbase_a - sraw);
    uint32_t s_ctrl = sbase_a + OFF_CTRL;

    if (wid == 0) {
        asm volatile("tcgen05.alloc.cta_group::1.sync.aligned.shared::cta.b32 [%0], %1;"
                     :: "r"(s_ctrl), "r"(256u) : "memory");
        asm volatile("tcgen05.relinquish_alloc_permit.cta_group::1.sync.aligned;");
    }
    if (t == 0) {
        asm volatile("mbarrier.init.shared.b64 [%0], %1;" :: "r"(s_ctrl + 8),  "r"(1u) : "memory");
        asm volatile("mbarrier.init.shared.b64 [%0], %1;" :: "r"(s_ctrl + 16), "r"(1u) : "memory");
        asm volatile("mbarrier.init.shared.b64 [%0], %1;" :: "r"(s_ctrl + 24), "r"(1u) : "memory");
        asm volatile("mbarrier.init.shared.b64 [%0], %1;" :: "r"(s_ctrl + 32), "r"(256u) : "memory");
        asm volatile("mbarrier.init.shared.b64 [%0], %1;" :: "r"(s_ctrl + 40), "r"(256u) : "memory");
    }
    __syncthreads();
    uint32_t tmem;
    asm volatile("ld.shared.b32 %0, [%1];" : "=r"(tmem) : "r"(s_ctrl));

    if (wid < 8) {
        // ======================= PRODUCER (threads 0..255) ===================
        int cur_e = -1;
        for (int tile = begin; tile < end; tile++) {
            int e = 0;
            while (tile >= pfx[e + 1]) e++;
            int m0 = (tile - pfx[e]) * BM;
            int nr = min(BM, c[e] - m0);
            int rel = tile - begin;
            int stg = rel % NSTG;
            int n3  = rel / NSTG;
            int buf = rel & 1;

            // ring stage free? (MMA of tile rel-3 must have read it)
            if (rel >= NSTG)
                mbar_wait(s_ctrl + 8 + 8u * (uint32_t)stg, (uint32_t)((n3 - 1) & 1));

            // Expert change: W TMEM read by MMA(rel-1) -> wait it, reload W
            if (e != cur_e) {
                if (rel >= 1) {
                    int pr = rel - 1;
                    mbar_wait(s_ctrl + 8 + 8u * (uint32_t)(pr % NSTG),
                              (uint32_t)((pr / NSTG) & 1));
                }
                if (t < 128) {
                    int o = t;
                    uint32_t woff = ((uint32_t)(t >> 5)) << 21;
#pragma unroll
                    for (int half = 0; half < 2; half++) {
                        const unsigned char* img = half ? g_wimg_lo[e] : g_wimg_hi[e];
#pragma unroll
                        for (int part = 0; part < 2; part++) {
                            uint32_t r[32];
#pragma unroll
                            for (int c8 = 0; c8 < 8; c8++) {
                                uint4 v = *(const uint4*)(img +
                                    swz(tile_off_128r((uint32_t)o,
                                        (uint32_t)((part * 8 + c8) * 8))));
                                r[c8*4+0] = v.x; r[c8*4+1] = v.y;
                                r[c8*4+2] = v.z; r[c8*4+3] = v.w;
                            }
                            uint32_t addr = tmem + (half ? TM_WLO : TM_WHI) +
                                            (uint32_t)part * 32u + woff;
                            asm volatile(
                                "tcgen05.st.sync.aligned.32x32b.x32.b32 [%0], "
                                "{%1, %2, %3, %4, %5, %6, %7, %8, "
                                " %9, %10, %11, %12, %13, %14, %15, %16, "
                                " %17, %18, %19, %20, %21, %22, %23, %24, "
                                " %25, %26, %27, %28, %29, %30, %31, %32};"
                                :: "r"(addr),
                                   "r"(r[0]),  "r"(r[1]),  "r"(r[2]),  "r"(r[3]),
                                   "r"(r[4]),  "r"(r[5]),  "r"(r[6]),  "r"(r[7]),
                                   "r"(r[8]),  "r"(r[9]),  "r"(r[10]), "r"(r[11]),
                                   "r"(r[12]), "r"(r[13]), "r"(r[14]), "r"(r[15]),
                                   "r"(r[16]), "r"(r[17]), "r"(r[18]), "r"(r[19]),
                                   "r"(r[20]), "r"(r[21]), "r"(r[22]), "r"(r[23]),
                                   "r"(r[24]), "r"(r[25]), "r"(r[26]), "r"(r[27]),
                                   "r"(r[28]), "r"(r[29]), "r"(r[30]), "r"(r[31])
                                : "memory");
                        }
                    }
                    asm volatile("tcgen05.wait::st.sync.aligned;" ::: "memory");
                    asm volatile("tcgen05.fence::before_thread_sync;" ::: "memory");
                }
                asm volatile("bar.sync 1, 256;" ::: "memory");
                cur_e = e;
            }

            // Gather 8 rows per warp (two 4-row groups); lane l reads float4 l
            {
                int rbase = wid * 8;
                int gidx = 0;
                if (lane < 8) {
                    int rr = rbase + lane;
                    gidx = (rr < nr) ? __ldg(&g_row_idx[e][m0 + rr]) : 0;
                }
                unsigned char* ah = sm + OFF_A(stg);
                unsigned char* al = ah + 16384;
#pragma unroll
                for (int grp = 0; grp < 2; grp++) {
                    int rws[4];
                    float4 f[4];
#pragma unroll
                    for (int r = 0; r < 4; r++)
                        rws[r] = __shfl_sync(0xffffffffu, gidx, grp * 4 + r);
#pragma unroll
                    for (int r = 0; r < 4; r++)
                        f[r] = ((const float4*)(x + (size_t)rws[r] * CI))[lane];
#pragma unroll
                    for (int r = 0; r < 4; r++) {
                        int row = rbase + grp * 4 + r;
                        uint2 vh, vl;
                        split2(vh.x, vl.x, f[r].x, f[r].y);
                        split2(vh.y, vl.y, f[r].z, f[r].w);
                        uint32_t off = ((uint32_t)(row >> 3) + (uint32_t)(lane >> 4) * 8u) * 1024u +
                                       (row & 7u) * 128u + (uint32_t)(lane & 15u) * 8u;
                        uint32_t s = swz(off);
                        *(uint2*)(ah + s) = vh;
                        *(uint2*)(al + s) = vl;
                    }
                }
            }

            asm volatile("fence.proxy.async.shared::cta;" ::: "memory");
            asm volatile("bar.sync 1, 256;" ::: "memory");

            if (t == 0) {
                // D[buf] free? (consumers must have read tile rel-2's D)
                if (rel >= 2)
                    mbar_wait(s_ctrl + 32 + 8u * (uint32_t)buf,
                              (uint32_t)(((rel - 2) >> 1) & 1));
                asm volatile("tcgen05.fence::after_thread_sync;" ::: "memory");
                uint64_t dxh = make_desc(sbase_a + OFF_A(stg));
                uint64_t dxl = make_desc(sbase_a + OFF_A(stg) + 16384u);
                uint32_t ta[3] = {tmem + TM_WHI, tmem + TM_WHI, tmem + TM_WLO};
                uint64_t tb[3] = {dxh, dxl, dxh};
                uint32_t td = tmem + (uint32_t)buf * 64u;
                uint32_t en = 0;
#pragma unroll
                for (int term = 0; term < 3; term++) {
#pragma unroll
                    for (int k = 0; k < 8; k++) {
                        uint32_t a_tm = ta[term] + (uint32_t)k * 8u;
                        // 64-row tile: atom-col stride = 8 atoms = 8192B = 512 units
                        uint64_t b_ds = tb[term] + (uint64_t)((k >> 2) * 512 + (k & 3) * 2);
                        asm volatile(
                            "{\n\t.reg .pred p;\n\t"
                            "setp.ne.u32 p, %4, 0;\n\t"
                            "tcgen05.mma.cta_group::1.kind::f16 [%0], [%1], %2, %3, {%5, %5, %5, %5}, p;\n\t}"
                            :: "r"(td), "r"(a_tm), "l"(b_ds),
                               "r"(MMA_IDESC), "r"(en), "r"(0u) : "memory");
                        en = 1;
                    }
                }
                asm volatile(
                    "tcgen05.commit.cta_group::1.mbarrier::arrive::one.shared::cluster.b64 [%0];"
                    :: "r"(s_ctrl + 8 + 8u * (uint32_t)stg) : "memory");
            }
        }
    } else {
        // ======================= CONSUMER (threads 256..511) =================
        // warp: output channels o = sub*32+lane (TMEM lanes), cols ch*32..+31.
        int cw = wid - 8, sub = wid & 3, ch = (wid >> 2) & 1;

        // This warp's static slice of unmatched rows (zeroed interleaved).
        int zw0 = z0 + (int)((long long)(z1 - z0) * cw / 8);
        int zw1 = z0 + (int)((long long)(z1 - z0) * (cw + 1) / 8);
        int zp = zw0;
        float4 zz = make_float4(0.f, 0.f, 0.f, 0.f);

        float breg = 0.f;
        int cur_e = -1;
        for (int tile = begin; tile < end; tile++) {
            int e = 0;
            while (tile >= pfx[e + 1]) e++;
            int m0 = (tile - pfx[e]) * BM;
            int nr = min(BM, c[e] - m0);
            int rel = tile - begin;
            int stg = rel % NSTG;
            int n3  = rel / NSTG;
            int buf = rel & 1;

            if (e != cur_e) {
                breg = __ldg(bias + e * CO + sub * 32 + lane);
                cur_e = e;
            }

            // Prefetch this tile's row indices (latency hidden by mbar wait).
            int i0 = __ldg(&g_row_idx[e][m0 + ch * 32 + lane]);

            mbar_wait(s_ctrl + 8 + 8u * (uint32_t)stg, (uint32_t)(n3 & 1));
            asm volatile("tcgen05.fence::after_thread_sync;" ::: "memory");

            uint32_t d[32];
            uint32_t td = tmem + (uint32_t)buf * 64u + (uint32_t)ch * 32u;
            asm volatile(
                "tcgen05.ld.sync.aligned.32x32b.x32.b32 "
                "{%0, %1, %2, %3, %4, %5, %6, %7, "
                " %8, %9, %10, %11, %12, %13, %14, %15, "
                " %16, %17, %18, %19, %20, %21, %22, %23, "
                " %24, %25, %26, %27, %28, %29, %30, %31}, [%32];"
                : "=r"(d[0]),  "=r"(d[1]),  "=r"(d[2]),  "=r"(d[3]),
                  "=r"(d[4]),  "=r"(d[5]),  "=r"(d[6]),  "=r"(d[7]),
                  "=r"(d[8]),  "=r"(d[9]),  "=r"(d[10]), "=r"(d[11]),
                  "=r"(d[12]), "=r"(d[13]), "=r"(d[14]), "=r"(d[15]),
                  "=r"(d[16]), "=r"(d[17]), "=r"(d[18]), "=r"(d[19]),
                  "=r"(d[20]), "=r"(d[21]), "=r"(d[22]), "=r"(d[23]),
                  "=r"(d[24]), "=r"(d[25]), "=r"(d[26]), "=r"(d[27]),
                  "=r"(d[28]), "=r"(d[29]), "=r"(d[30]), "=r"(d[31])
                : "r"(td));
            asm volatile("tcgen05.wait::ld.sync.aligned;" ::: "memory");

            // D[buf] fully read -> release to producer (before the stores).
            asm volatile("mbarrier.arrive.shared.b64 _, [%0];"
                         :: "r"(s_ctrl + 32 + 8u * (uint32_t)buf) : "memory");

            // Store: col j = gathered row ch*32+j; 32 lanes = one 128B line.
            float* ob = out + sub * 32 + lane;
            if (nr == BM) {
#pragma unroll
                for (int j = 0; j < 32; j++) {
                    int grow = __shfl_sync(0xffffffffu, i0, j);
                    ob[(size_t)grow * CO] = fmaxf(__uint_as_float(d[j]) + breg, 0.f);
                }
            } else {
#pragma unroll
                for (int j = 0; j < 32; j++) {
                    int m = ch * 32 + j;
                    if (m < nr) {
                        int grow = __shfl_sync(0xffffffffu, i0, j);
                        ob[(size_t)grow * CO] = fmaxf(__uint_as_float(d[j]) + breg, 0.f);
                    }
                }
            }

            // ---- interleaved zero chunk: up to 32 unmatched rows ------------
            if (zp < zw1) {
                int n = min(32, zw1 - zp);
                int gz = (lane < n) ? __ldg(&g_row_idx[4][zp + lane]) : 0;
#pragma unroll 8
                for (int j = 0; j < 32; j++) {
                    if (j < n) {
                        int grow = __shfl_sync(0xffffffffu, gz, j);
                        ((float4*)out)[(size_t)grow * 32 + lane] = zz;
                    }
                }
                zp += n;
            }
        }

        // ---- flush remaining unmatched rows ---------------------------------
        while (zp < zw1) {
            int n = min(32, zw1 - zp);
            int gz = (lane < n) ? __ldg(&g_row_idx[4][zp + lane]) : 0;
#pragma unroll 8
            for (int j = 0; j < 32; j++) {
                if (j < n) {
                    int grow = __shfl_sync(0xffffffffu, gz, j);
                    ((float4*)out)[(size_t)grow * 32 + lane] = zz;
                }
            }
            zp += n;
        }
    }

    __syncthreads();
    if (t == 0) {
        asm volatile("mbarrier.inval.shared.b64 [%0];" :: "r"(s_ctrl + 8) : "memory");
        asm volatile("mbarrier.inval.shared.b64 [%0];" :: "r"(s_ctrl + 16) : "memory");
        asm volatile("mbarrier.inval.shared.b64 [%0];" :: "r"(s_ctrl + 24) : "memory");
        asm volatile("mbarrier.inval.shared.b64 [%0];" :: "r"(s_ctrl + 32) : "memory");
        asm volatile("mbarrier.inval.shared.b64 [%0];" :: "r"(s_ctrl + 40) : "memory");
    }
    __syncthreads();
    if (wid == 0) {
        asm volatile("tcgen05.dealloc.cta_group::1.sync.aligned.b32 %0, %1;"
                     :: "r"(tmem), "r"(256u));
    }
    if (blockIdx.x == 0 && t < NB) g_count[t] = 0;   // for next invocation
#endif
}

// ---------------- launch -----------------------------------------------------
extern "C" void kernel_launch(void* const* d_in, const int* in_sizes, int n_in,
                              void* d_out, int out_size) {
    const float* x = (const float*)d_in[0];
    const int* atom_numbers = (const int*)d_in[1];
    const float* W = (const float*)d_in[2];
    const float* bias = (const float*)d_in[3];
    const int* atom_cases = (const int*)d_in[4];
    float* out = (float*)d_out;

    int nrows = in_sizes[1];  // B * A
    int nscatter = (nrows + 1023) / 1024;

    k_prep<<<nscatter + NE, 1024>>>(atom_numbers, atom_cases, W, nrows, nscatter);

    cudaFuncSetAttribute(k_gemm, cudaFuncAttributeMaxDynamicSharedMemorySize, SMEM_BYTES);
    k_gemm<<<NCTA, NT, SMEM_BYTES>>>(x, W, bias, out);
}

// round 17
// speedup vs baseline: 1.1103x; 1.1103x over previous
#include <cuda_runtime.h>
#include <cuda_bf16.h>
#include <cstdint>

#define CI 128
#define CO 128
#define NE 4
#define NB 5               // 4 experts + 1 "unmatched" bucket
#define MAXROWS (2048*128)
#define BM 128
#define NCTA 152            // persistent grid (GB300: 152 SMs)
#define NT 512              // 8 producer warps + 8 consumer warps
#define NSTG 3              // x-tile ring depth == D ring depth

// ---------------- scratch (__device__ globals; no dynamic alloc allowed) ----
__device__ int g_row_idx[NB][MAXROWS];
__device__ int g_count[NB];   // zeroed at load; re-zeroed by k_gemm tail
__device__ __align__(16) unsigned char g_wimg_hi[NE][32768];
__device__ __align__(16) unsigned char g_wimg_lo[NE][32768];

// ---------------- small helpers ---------------------------------------------
__device__ __forceinline__ uint32_t smem_u32(const void* p) {
    uint32_t a;
    asm("{ .reg .u64 t; cvta.to.shared.u64 t, %1; cvt.u32.u64 %0, t; }"
        : "=r"(a) : "l"(p));
    return a;
}
__device__ __forceinline__ uint32_t swz(uint32_t off) {   // SW128: Swizzle<3,4,3>
    return off ^ ((off >> 3) & 0x70);
}
__device__ __forceinline__ void split2(uint32_t& h, uint32_t& l, float a, float b) {
    asm("cvt.rn.bf16x2.f32 %0, %1, %2;" : "=r"(h) : "f"(b), "f"(a));
    float ra = a - __uint_as_float(h << 16);
    float rb = b - __uint_as_float(h & 0xffff0000u);
    asm("cvt.rn.bf16x2.f32 %0, %1, %2;" : "=r"(l) : "f"(rb), "f"(ra));
}
static __device__ __forceinline__ uint64_t make_desc(uint32_t addr) {
    const uint64_t BASE = (uint64_t(2) << 61) | (uint64_t(1) << 46) |
                          (uint64_t(64) << 32) | (uint64_t(1) << 16);
    return BASE | ((uint64_t)(addr >> 4) & 0x3FFF);
}
#define MMA_IDESC 0x8200490u          // f32 accum, bf16 a/b, M=128, N=128
__device__ __forceinline__ uint32_t tile_off_128r(uint32_t row, uint32_t col) {
    return ((row >> 3) + (col >> 6) * 16u) * 1024u + (row & 7u) * 128u + (col & 63u) * 2u;
}
__device__ __forceinline__ void mbar_wait(uint32_t mb, uint32_t par) {
    uint32_t done = 0;
    while (!done) {
        asm volatile(
            "{\n\t.reg .pred p;\n\t"
            "mbarrier.try_wait.parity.acquire.cta.shared::cta.b64 p, [%1], %2, 0x989680;\n\t"
            "selp.b32 %0, 1, 0, p;\n\t}"
            : "=r"(done) : "r"(mb), "r"(par) : "memory");
    }
}

// ---------------- prep: scatter blocks + wprep blocks (NO zeroing) -----------
__global__ void __launch_bounds__(1024)
k_prep(const int* __restrict__ atom_numbers, const int* __restrict__ atom_cases,
       const float* __restrict__ W, int nrows, int nscatter) {
    if ((int)blockIdx.x >= nscatter) {
        int e = blockIdx.x - nscatter;
        const float* We = W + (size_t)e * CI * CO;
        for (int item = threadIdx.x; item < CO * 16; item += 1024) {
            int o = item & 127;
            int kc = item >> 7;
            uint32_t ph[4], pl[4];
#pragma unroll
            for (int j = 0; j < 4; j++) {
                float a = __ldg(We + (kc * 8 + 2 * j) * CO + o);
                float b = __ldg(We + (kc * 8 + 2 * j + 1) * CO + o);
                split2(ph[j], pl[j], a, b);
            }
            uint32_t s = swz(tile_off_128r(o, kc * 8));
            *(uint4*)((unsigned char*)g_wimg_hi[e] + s) =
                make_uint4(ph[0], ph[1], ph[2], ph[3]);
            *(uint4*)((unsigned char*)g_wimg_lo[e] + s) =
                make_uint4(pl[0], pl[1], pl[2], pl[3]);
        }
        return;
    }

    __shared__ int wcnt[NB][32];
    __shared__ int sbase[NB];
    int t = threadIdx.x, w = t >> 5, lane = t & 31;
    int row = blockIdx.x * 1024 + t;
    bool valid = row < nrows;
    int an = valid ? atom_numbers[row] : -1234567;
    int c0 = __ldg(atom_cases + 0), c1 = __ldg(atom_cases + 1);
    int c2 = __ldg(atom_cases + 2), c3 = __ldg(atom_cases + 3);
    int e = 4;
    if (an == c0) e = 0;
    else if (an == c1) e = 1;
    else if (an == c2) e = 2;
    else if (an == c3) e = 3;
    if (!valid) e = -1;

    int myrank = 0;
#pragma unroll
    for (int b = 0; b < NB; b++) {
        unsigned m = __ballot_sync(0xffffffffu, e == b);
        if (e == b) myrank = __popc(m & ((1u << lane) - 1u));
        if (lane == 0) wcnt[b][w] = __popc(m);
    }
    __syncthreads();
    if (t < NB) {
        int s = 0;
#pragma unroll
        for (int i = 0; i < 32; i++) { int v = wcnt[t][i]; wcnt[t][i] = s; s += v; }
        sbase[t] = s ? atomicAdd(&g_count[t], s) : 0;
    }
    __syncthreads();
    if (e >= 0) g_row_idx[e][sbase[e] + wcnt[e][w] + myrank] = row;
}

// ---------------- warp-specialized persistent grouped GEMM (TS, BM=128) -------
// W in TMEM (A operand): W_hi at 384, W_lo at 448. D ring 3-deep at 0/128/256.
// x tiles in a 3-deep smem ring. Gather issues all 16 row-loads per warp
// before converting (MLP 16). Consumers zero unmatched rows interleaved.
// mma_mbar[s], s=0..2 (count 1): MMA commit of tile using ring stage s;
//   tile rel uses s=rel%3, completion n=rel/3 lands on parity n&1.
// epi_mbar[s], s=0..2 (count 256): consumers done reading D[s].
#define OFF_A(stg)  ((stg) * 65536u)            // x_hi at +0, x_lo at +32768
#define OFF_CTRL 196608u   // [0]=tmem [8,16,24]=mma mbars [32,40,48]=epi mbars
#define SMEM_BYTES (196608 + 1024 + 1024)
#define TM_WHI 384u
#define TM_WLO 448u

__global__ void __launch_bounds__(NT, 1)
k_gemm(const float* __restrict__ x, const float* __restrict__ W,
       const float* __restrict__ bias, float* __restrict__ out) {
    int t = threadIdx.x;
    int wid = t >> 5, lane = t & 31;

    int c[NE], pfx[NE + 1];
    pfx[0] = 0;
#pragma unroll
    for (int e = 0; e < NE; e++) {
        c[e] = g_count[e];
        pfx[e + 1] = pfx[e] + ((c[e] + BM - 1) >> 7);
    }
    int total = pfx[NE];
    int begin = (int)((long long)total * blockIdx.x / gridDim.x);
    int end   = (int)((long long)total * (blockIdx.x + 1) / gridDim.x);

    // unmatched-row zero slice for this CTA
    int cnt4 = g_count[4];
    int z0 = (int)((long long)cnt4 * blockIdx.x / gridDim.x);
    int z1 = (int)((long long)cnt4 * (blockIdx.x + 1) / gridDim.x);

#if defined(__CUDA_ARCH__) && !defined(__CUDA_ARCH_FEAT_SM103_ALL)
    // ---------------- fallback: fp32 SIMT (JIT-safety only) ------------------
    for (int i = z0 * 32 + t; i < z1 * 32; i += NT) {
        int grow = g_row_idx[4][i >> 5];
        ((float4*)out)[(size_t)grow * 32 + (i & 31)] = make_float4(0.f, 0.f, 0.f, 0.f);
    }
    for (int tile = begin; tile < end; tile++) {
        int e = 0;
        while (tile >= pfx[e + 1]) e++;
        int m0 = (tile - pfx[e]) * BM;
        int nr = min(BM, c[e] - m0);
        for (int idx = t; idx < nr * CO; idx += NT) {
            int m = idx >> 7, o = idx & 127;
            int grow = g_row_idx[e][m0 + m];
            const float* xr = x + (size_t)grow * CI;
            const float* wc = W + (size_t)e * CI * CO + o;
            float acc = bias[e * CO + o];
            for (int k = 0; k < CI; k++) acc += xr[k] * wc[(size_t)k * CO];
            out[(size_t)grow * CO + o] = fmaxf(acc, 0.f);
        }
    }
    __syncthreads();
    if (blockIdx.x == 0 && t < NB) g_count[t] = 0;
#else
    extern __shared__ unsigned char smraw[];
    uint32_t sraw = smem_u32(smraw);
    uint32_t sbase_a = (sraw + 1023u) & ~1023u;
    unsigned char* sm = smraw + (sbase_a - sraw);
    uint32_t s_ctrl = sbase_a + OFF_CTRL;

    if (wid == 0) {
        asm volatile("tcgen05.alloc.cta_group::1.sync.aligned.shared::cta.b32 [%0], %1;"
                     :: "r"(s_ctrl), "r"(512u) : "memory");
        asm volatile("tcgen05.relinquish_alloc_permit.cta_group::1.sync.aligned;");
    }
    if (t == 0) {
#pragma unroll
        for (int i = 0; i < 3; i++) {
            asm volatile("mbarrier.init.shared.b64 [%0], %1;"
                         :: "r"(s_ctrl + 8 + 8u * i), "r"(1u) : "memory");
            asm volatile("mbarrier.init.shared.b64 [%0], %1;"
                         :: "r"(s_ctrl + 32 + 8u * i), "r"(256u) : "memory");
        }
    }
    __syncthreads();
    uint32_t tmem;
    asm volatile("ld.shared.b32 %0, [%1];" : "=r"(tmem) : "r"(s_ctrl));

    if (wid < 8) {
        // ======================= PRODUCER (threads 0..255) ===================
        int cur_e = -1;
        for (int tile = begin; tile < end; tile++) {
            int e = 0;
            while (tile >= pfx[e + 1]) e++;
            int m0 = (tile - pfx[e]) * BM;
            int nr = min(BM, c[e] - m0);
            int rel = tile - begin;
            int stg = rel % NSTG;
            int n3  = rel / NSTG;

            // ring stage free? (MMA of tile rel-3 must have read it)
            if (rel >= NSTG)
                mbar_wait(s_ctrl + 8 + 8u * (uint32_t)stg, (uint32_t)((n3 - 1) & 1));

            // Expert change: W TMEM read by MMA(rel-1) -> wait it, reload W
            if (e != cur_e) {
                if (rel >= 1) {
                    int pr = rel - 1;
                    mbar_wait(s_ctrl + 8 + 8u * (uint32_t)(pr % NSTG),
                              (uint32_t)((pr / NSTG) & 1));
                }
                if (t < 128) {
                    int o = t;
                    uint32_t woff = ((uint32_t)(t >> 5)) << 21;
#pragma unroll
                    for (int half = 0; half < 2; half++) {
                        const unsigned char* img = half ? g_wimg_lo[e] : g_wimg_hi[e];
#pragma unroll
                        for (int part = 0; part < 2; part++) {
                            uint32_t r[32];
#pragma unroll
                            for (int c8 = 0; c8 < 8; c8++) {
                                uint4 v = *(const uint4*)(img +
                                    swz(tile_off_128r((uint32_t)o,
                                        (uint32_t)((part * 8 + c8) * 8))));
                                r[c8*4+0] = v.x; r[c8*4+1] = v.y;
                                r[c8*4+2] = v.z; r[c8*4+3] = v.w;
                            }
                            uint32_t addr = tmem + (half ? TM_WLO : TM_WHI) +
                                            (uint32_t)part * 32u + woff;
                            asm volatile(
                                "tcgen05.st.sync.aligned.32x32b.x32.b32 [%0], "
                                "{%1, %2, %3, %4, %5, %6, %7, %8, "
                                " %9, %10, %11, %12, %13, %14, %15, %16, "
                                " %17, %18, %19, %20, %21, %22, %23, %24, "
                                " %25, %26, %27, %28, %29, %30, %31, %32};"
                                :: "r"(addr),
                                   "r"(r[0]),  "r"(r[1]),  "r"(r[2]),  "r"(r[3]),
                                   "r"(r[4]),  "r"(r[5]),  "r"(r[6]),  "r"(r[7]),
                                   "r"(r[8]),  "r"(r[9]),  "r"(r[10]), "r"(r[11]),
                                   "r"(r[12]), "r"(r[13]), "r"(r[14]), "r"(r[15]),
                                   "r"(r[16]), "r"(r[17]), "r"(r[18]), "r"(r[19]),
                                   "r"(r[20]), "r"(r[21]), "r"(r[22]), "r"(r[23]),
                                   "r"(r[24]), "r"(r[25]), "r"(r[26]), "r"(r[27]),
                                   "r"(r[28]), "r"(r[29]), "r"(r[30]), "r"(r[31])
                                : "memory");
                        }
                    }
                    asm volatile("tcgen05.wait::st.sync.aligned;" ::: "memory");
                    asm volatile("tcgen05.fence::before_thread_sync;" ::: "memory");
                }
                asm volatile("bar.sync 1, 256;" ::: "memory");
                cur_e = e;
            }

            // Gather 16 rows per warp; ALL loads issued before converts (MLP 16)
            {
                int rbase = wid * 16;
                int gidx = 0;
                if (lane < 16) {
                    int rr = rbase + lane;
                    gidx = (rr < nr) ? __ldg(&g_row_idx[e][m0 + rr]) : 0;
                }
                int rws[16];
#pragma unroll
                for (int r = 0; r < 16; r++)
                    rws[r] = __shfl_sync(0xffffffffu, gidx, r);
                float4 f[16];
#pragma unroll
                for (int r = 0; r < 16; r++)
                    f[r] = ((const float4*)(x + (size_t)rws[r] * CI))[lane];
                unsigned char* ah = sm + OFF_A(stg);
                unsigned char* al = ah + 32768;
#pragma unroll
                for (int r = 0; r < 16; r++) {
                    int row = rbase + r;
                    uint2 vh, vl;
                    split2(vh.x, vl.x, f[r].x, f[r].y);
                    split2(vh.y, vl.y, f[r].z, f[r].w);
                    uint32_t off = ((uint32_t)(row >> 3) + (uint32_t)(lane >> 4) * 16u) * 1024u +
                                   (row & 7u) * 128u + (uint32_t)(lane & 15u) * 8u;
                    uint32_t s = swz(off);
                    *(uint2*)(ah + s) = vh;
                    *(uint2*)(al + s) = vl;
                }
            }

            asm volatile("fence.proxy.async.shared::cta;" ::: "memory");
            asm volatile("bar.sync 1, 256;" ::: "memory");

            if (t == 0) {
                // D[stg] free? (consumers must have read tile rel-3's D)
                if (rel >= NSTG)
                    mbar_wait(s_ctrl + 32 + 8u * (uint32_t)stg,
                              (uint32_t)((n3 - 1) & 1));
                asm volatile("tcgen05.fence::after_thread_sync;" ::: "memory");
                uint64_t dxh = make_desc(sbase_a + OFF_A(stg));
                uint64_t dxl = make_desc(sbase_a + OFF_A(stg) + 32768u);
                uint32_t ta[3] = {tmem + TM_WHI, tmem + TM_WHI, tmem + TM_WLO};
                uint64_t tb[3] = {dxh, dxl, dxh};
                uint32_t td = tmem + (uint32_t)stg * 128u;
                uint32_t en = 0;
#pragma unroll
                for (int term = 0; term < 3; term++) {
#pragma unroll
                    for (int k = 0; k < 8; k++) {
                        uint32_t a_tm = ta[term] + (uint32_t)k * 8u;
                        uint64_t b_ds = tb[term] + (uint64_t)((k >> 2) * 1024 + (k & 3) * 2);
                        asm volatile(
                            "{\n\t.reg .pred p;\n\t"
                            "setp.ne.u32 p, %4, 0;\n\t"
                            "tcgen05.mma.cta_group::1.kind::f16 [%0], [%1], %2, %3, {%5, %5, %5, %5}, p;\n\t}"
                            :: "r"(td), "r"(a_tm), "l"(b_ds),
                               "r"(MMA_IDESC), "r"(en), "r"(0u) : "memory");
                        en = 1;
                    }
                }
                asm volatile(
                    "tcgen05.commit.cta_group::1.mbarrier::arrive::one.shared::cluster.b64 [%0];"
                    :: "r"(s_ctrl + 8 + 8u * (uint32_t)stg) : "memory");
            }
        }
    } else {
        // ======================= CONSUMER (threads 256..511) =================
        int cw = wid - 8, sub = wid & 3, ch = (wid >> 2) & 1;

        // This warp's static slice of unmatched rows (zeroed interleaved).
        int zw0 = z0 + (int)((long long)(z1 - z0) * cw / 8);
        int zw1 = z0 + (int)((long long)(z1 - z0) * (cw + 1) / 8);
        int zp = zw0;
        float4 zz = make_float4(0.f, 0.f, 0.f, 0.f);

        float breg = 0.f;
        int cur_e = -1;
        for (int tile = begin; tile < end; tile++) {
            int e = 0;
            while (tile >= pfx[e + 1]) e++;
            int m0 = (tile - pfx[e]) * BM;
            int nr = min(BM, c[e] - m0);
            int rel = tile - begin;
            int stg = rel % NSTG;
            int n3  = rel / NSTG;

            if (e != cur_e) {
                breg = __ldg(bias + e * CO + sub * 32 + lane);
                cur_e = e;
            }

            // Prefetch this tile's row indices (latency hidden by mbar wait).
            int i0 = __ldg(&g_row_idx[e][m0 + ch * 64 + lane]);
            int i1 = __ldg(&g_row_idx[e][m0 + ch * 64 + 32 + lane]);

            mbar_wait(s_ctrl + 8 + 8u * (uint32_t)stg, (uint32_t)(n3 & 1));
            asm volatile("tcgen05.fence::after_thread_sync;" ::: "memory");

            uint32_t d[64];
            uint32_t td = tmem + (uint32_t)stg * 128u + (uint32_t)ch * 64u;
#pragma unroll
            for (int b = 0; b < 2; b++) {
                asm volatile(
                    "tcgen05.ld.sync.aligned.32x32b.x32.b32 "
                    "{%0, %1, %2, %3, %4, %5, %6, %7, "
                    " %8, %9, %10, %11, %12, %13, %14, %15, "
                    " %16, %17, %18, %19, %20, %21, %22, %23, "
                    " %24, %25, %26, %27, %28, %29, %30, %31}, [%32];"
                    : "=r"(d[b*32+0]),  "=r"(d[b*32+1]),  "=r"(d[b*32+2]),  "=r"(d[b*32+3]),
                      "=r"(d[b*32+4]),  "=r"(d[b*32+5]),  "=r"(d[b*32+6]),  "=r"(d[b*32+7]),
                      "=r"(d[b*32+8]),  "=r"(d[b*32+9]),  "=r"(d[b*32+10]), "=r"(d[b*32+11]),
                      "=r"(d[b*32+12]), "=r"(d[b*32+13]), "=r"(d[b*32+14]), "=r"(d[b*32+15]),
                      "=r"(d[b*32+16]), "=r"(d[b*32+17]), "=r"(d[b*32+18]), "=r"(d[b*32+19]),
                      "=r"(d[b*32+20]), "=r"(d[b*32+21]), "=r"(d[b*32+22]), "=r"(d[b*32+23]),
                      "=r"(d[b*32+24]), "=r"(d[b*32+25]), "=r"(d[b*32+26]), "=r"(d[b*32+27]),
                      "=r"(d[b*32+28]), "=r"(d[b*32+29]), "=r"(d[b*32+30]), "=r"(d[b*32+31])
                    : "r"(td + (uint32_t)b * 32u));
            }
            asm volatile("tcgen05.wait::ld.sync.aligned;" ::: "memory");

            // D[stg] fully read -> release to producer (before the stores).
            asm volatile("mbarrier.arrive.shared.b64 _, [%0];"
                         :: "r"(s_ctrl + 32 + 8u * (uint32_t)stg) : "memory");

            // Store: col j = gathered row ch*64+j; 32 lanes = one 128B line.
            float* ob = out + sub * 32 + lane;
            if (nr == BM) {
#pragma unroll
                for (int j = 0; j < 64; j++) {
                    int grow = __shfl_sync(0xffffffffu, (j < 32) ? i0 : i1, j & 31);
                    ob[(size_t)grow * CO] = fmaxf(__uint_as_float(d[j]) + breg, 0.f);
                }
            } else {
#pragma unroll
                for (int j = 0; j < 64; j++) {
                    int m = ch * 64 + j;
                    if (m < nr) {
                        int grow = __shfl_sync(0xffffffffu, (j < 32) ? i0 : i1, j & 31);
                        ob[(size_t)grow * CO] = fmaxf(__uint_as_float(d[j]) + breg, 0.f);
                    }
                }
            }

            // ---- interleaved zero chunk: up to 32 unmatched rows ------------
            if (zp < zw1) {
                int n = min(32, zw1 - zp);
                int gz = (lane < n) ? __ldg(&g_row_idx[4][zp + lane]) : 0;
#pragma unroll 8
                for (int j = 0; j < 32; j++) {
                    if (j < n) {
                        int grow = __shfl_sync(0xffffffffu, gz, j);
                        ((float4*)out)[(size_t)grow * 32 + lane] = zz;
                    }
                }
                zp += n;
            }
        }

        // ---- flush remaining unmatched rows ---------------------------------
        while (zp < zw1) {
            int n = min(32, zw1 - zp);
            int gz = (lane < n) ? __ldg(&g_row_idx[4][zp + lane]) : 0;
#pragma unroll 8
            for (int j = 0; j < 32; j++) {
                if (j < n) {
                    int grow = __shfl_sync(0xffffffffu, gz, j);
                    ((float4*)out)[(size_t)grow * 32 + lane] = zz;
                }
            }
            zp += n;
        }
    }

    __syncthreads();
    if (t == 0) {
#pragma unroll
        for (int i = 0; i < 3; i++) {
            asm volatile("mbarrier.inval.shared.b64 [%0];"
                         :: "r"(s_ctrl + 8 + 8u * i) : "memory");
            asm volatile("mbarrier.inval.shared.b64 [%0];"
                         :: "r"(s_ctrl + 32 + 8u * i) : "memory");
        }
    }
    __syncthreads();
    if (wid == 0) {
        asm volatile("tcgen05.dealloc.cta_group::1.sync.aligned.b32 %0, %1;"
                     :: "r"(tmem), "r"(512u));
    }
    if (blockIdx.x == 0 && t < NB) g_count[t] = 0;   // for next invocation
#endif
}

// ---------------- launch -----------------------------------------------------
extern "C" void kernel_launch(void* const* d_in, const int* in_sizes, int n_in,
                              void* d_out, int out_size) {
    const float* x = (const float*)d_in[0];
    const int* atom_numbers = (const int*)d_in[1];
    const float* W = (const float*)d_in[2];
    const float* bias = (const float*)d_in[3];
    const int* atom_cases = (const int*)d_in[4];
    float* out = (float*)d_out;

    int nrows = in_sizes[1];  // B * A
    int nscatter = (nrows + 1023) / 1024;

    k_prep<<<nscatter + NE, 1024>>>(atom_numbers, atom_cases, W, nrows, nscatter);

    cudaFuncSetAttribute(k_gemm, cudaFuncAttributeMaxDynamicSharedMemorySize, SMEM_BYTES);
    k_gemm<<<NCTA, NT, SMEM_BYTES>>>(x, W, bias, out);
}